// round 12
// baseline (speedup 1.0000x reference)
#include <cuda_runtime.h>
#include <cuda_fp16.h>
#include <math.h>
#include <stdint.h>

// Problem dims (fixed by the dataset)
#define B_ROWS 32768
#define OBS_D  512
#define H1_D   1024
#define H2_D   1024
#define ACT_D  64
#define OUT3_D (2*ACT_D)   // 128

// Activation rescale: hidden activations (~2e-5) are fp16-subnormal, so store
// h*4096 (exact power of two) and fold 1/4096 into the next layer's scale.
#define HSCALE 4096.0f

// ---------------- device scratch (no allocs allowed) ----------------
__device__ __align__(256) __half g_xb[(size_t)B_ROWS * OBS_D];
__device__ __align__(256) __half g_h1[(size_t)B_ROWS * H1_D];
__device__ __align__(256) __half g_h2[(size_t)B_ROWS * H2_D];
__device__ __align__(256) __half g_w1[H1_D * OBS_D];     // int-valued quant weights (fp16-exact)
__device__ __align__(256) __half g_w2[H2_D * H1_D];
__device__ __align__(256) __half g_w3[OUT3_D * H2_D];
__device__ float g_b1q[H1_D], g_b2q[H2_D], g_b3q[OUT3_D];
__device__ float g_absmax[3];
__device__ float g_scales[3];

__device__ __forceinline__ uint32_t pack_h2(float lo, float hi) {
    uint32_t r;
    asm("cvt.rn.f16x2.f32 %0, %1, %2;" : "=r"(r) : "f"(hi), "f"(lo));
    return r;
}

// ---------------- prep kernels ----------------
__global__ void zero_absmax_kernel() {
    if (threadIdx.x < 3) g_absmax[threadIdx.x] = 0.0f;
}

// blocks [0,64)->W1  [64,192)->W2  [192,208)->W3
__global__ void absmax3_kernel(const float4* __restrict__ W1,
                               const float4* __restrict__ W2,
                               const float4* __restrict__ W3) {
    int b = blockIdx.x;
    const float4* W; int n4, nb, which;
    if (b < 64)       { W = W1; n4 = (H1_D * OBS_D) / 4; nb = 64;  which = 0; }
    else if (b < 192) { W = W2; n4 = (H2_D * H1_D) / 4;  nb = 128; which = 1; b -= 64; }
    else              { W = W3; n4 = (OUT3_D * H2_D) / 4; nb = 16; which = 2; b -= 192; }
    float m = 0.0f;
    for (int i = b * 256 + threadIdx.x; i < n4; i += nb * 256) {
        float4 v = W[i];
        m = fmaxf(m, fmaxf(fmaxf(fabsf(v.x), fabsf(v.y)), fmaxf(fabsf(v.z), fabsf(v.w))));
    }
    #pragma unroll
    for (int off = 16; off; off >>= 1)
        m = fmaxf(m, __shfl_xor_sync(0xffffffffu, m, off));
    if ((threadIdx.x & 31) == 0)
        atomicMax(reinterpret_cast<int*>(&g_absmax[which]), __float_as_int(m));
}

__global__ void prep_kernel(const float* __restrict__ b1,
                            const float* __restrict__ b2,
                            const float* __restrict__ b3) {
    const float s_in = 1.0f / 12000.0f;
    const float ws1 = g_absmax[0] * (1.0f / 127.0f);
    const float ws2 = g_absmax[1] * (1.0f / 127.0f);
    const float ws3 = g_absmax[2] * (1.0f / 127.0f);
    const int t = threadIdx.x;
    if (t == 0) {
        g_scales[0] = s_in * s_in * ws1 * HSCALE;  // layer1 out pre-scaled by 4096
        g_scales[1] = ws2;                          // 4096 in / 4096 out cancel
        g_scales[2] = ws3 / HSCALE;                 // undo input prescale
    }
    const float s1  = s_in * ws1;
    const float sb2 = s1 * ws2;
    const float s2  = s1 * ws2;
    const float sb3 = s2 * ws3;
    // biases for layers 1,2 folded with the 4096 output prescale (ReLU commutes)
    if (t < H1_D)   g_b1q[t] = fminf(fmaxf(rintf(b1[t] / s1),  -128.0f), 127.0f) * s1  * HSCALE;
    if (t < H2_D)   g_b2q[t] = fminf(fmaxf(rintf(b2[t] / sb2), -128.0f), 127.0f) * sb2 * HSCALE;
    if (t < OUT3_D) g_b3q[t] = fminf(fmaxf(rintf(b3[t] / sb3), -128.0f), 127.0f) * sb3;
}

__global__ void quant3_kernel(const float4* __restrict__ W1,
                              const float4* __restrict__ W2,
                              const float4* __restrict__ W3) {
    int b = blockIdx.x;
    const float4* W; uint2* O; int n4, nb, which;
    if (b < 64)       { W = W1; O = (uint2*)g_w1; n4 = (H1_D * OBS_D) / 4; nb = 64;  which = 0; }
    else if (b < 192) { W = W2; O = (uint2*)g_w2; n4 = (H2_D * H1_D) / 4;  nb = 128; which = 1; b -= 64; }
    else              { W = W3; O = (uint2*)g_w3; n4 = (OUT3_D * H2_D) / 4; nb = 16; which = 2; b -= 192; }
    const float inv = 127.0f / g_absmax[which];
    for (int i = b * 256 + threadIdx.x; i < n4; i += nb * 256) {
        float4 v = W[i];
        float q0 = fminf(fmaxf(rintf(v.x * inv), -127.0f), 127.0f);
        float q1 = fminf(fmaxf(rintf(v.y * inv), -127.0f), 127.0f);
        float q2 = fminf(fmaxf(rintf(v.z * inv), -127.0f), 127.0f);
        float q3 = fminf(fmaxf(rintf(v.w * inv), -127.0f), 127.0f);
        uint2 o;
        o.x = pack_h2(q0, q1);
        o.y = pack_h2(q2, q3);
        O[i] = o;
    }
}

__global__ void cvt_obs4_kernel(const float4* __restrict__ src, uint2* __restrict__ dst, int n4) {
    for (int i = blockIdx.x * blockDim.x + threadIdx.x; i < n4; i += gridDim.x * blockDim.x) {
        float4 v = src[i];
        uint2 o;
        o.x = pack_h2(v.x, v.y);
        o.y = pack_h2(v.z, v.w);
        dst[i] = o;
    }
}

// ============= BIG GEMM (layers 1,2): BM=BN=256, 512 threads, occ 1 =============
// C[M,N] = A[M,K] @ Bw[N,K]^T, fp16 in, fp16 acc, 3-stage cp.async (192KB smem).
// Warp layout 4x4, warp tile 64x64. Epilogue: scale*acc+bias, ReLU, fp16 store.
// L2 traffic halves vs 128x128 tiles -> attacks the LTS-bandwidth bound.

__global__ void __launch_bounds__(512, 1)
gemm_big(const __half* __restrict__ A,
         const __half* __restrict__ Bw,
         __half* __restrict__ C,
         const float* __restrict__ bias,
         const float* __restrict__ scale_p,
         int K, int Nst) {
    extern __shared__ char smem[];
    constexpr unsigned STG = 65536u;                 // 32KB A + 32KB B per stage
    const int tid  = threadIdx.x;
    const int lane = tid & 31;
    const int warp = tid >> 5;
    const int wm = (warp & 3) * 64;                  // 4 warps in M
    const int wn = (warp >> 2) * 64;                 // 4 warps in N
    const int bm = blockIdx.y * 256;
    const int bn = blockIdx.x * 256;
    const unsigned sbase = (unsigned)__cvta_generic_to_shared(smem);
    const int KT = K >> 6;

    auto load_tile = [&](int c) {
        const int st = c % 3;
        const __half* Ag = A + (size_t)bm * K + c * 64;
        const __half* Bg = Bw + (size_t)bn * K + c * 64;
        const unsigned as = sbase + st * STG;
        const unsigned bs = as + 32768u;
        #pragma unroll
        for (int i = 0; i < 4; i++) {                // A: 256 rows x 8 x 16B
            int idx = tid + i * 512;
            int row = idx >> 3, ch = idx & 7, sw = ch ^ (row & 7);
            asm volatile("cp.async.cg.shared.global [%0], [%1], 16;" ::
                "r"(as + row * 128u + sw * 16u), "l"(Ag + (size_t)row * K + ch * 8));
        }
        #pragma unroll
        for (int i = 0; i < 4; i++) {                // B: 256 rows x 8 x 16B
            int idx = tid + i * 512;
            int row = idx >> 3, ch = idx & 7, sw = ch ^ (row & 7);
            asm volatile("cp.async.cg.shared.global [%0], [%1], 16;" ::
                "r"(bs + row * 128u + sw * 16u), "l"(Bg + (size_t)row * K + ch * 8));
        }
    };

    // fp16 accumulators: warp tile 64x64 = 4 (mi) x 8 (ni) x 2 b32 regs
    uint32_t acc[4][8][2];
    #pragma unroll
    for (int mi = 0; mi < 4; mi++)
        #pragma unroll
        for (int ni = 0; ni < 8; ni++) { acc[mi][ni][0] = 0u; acc[mi][ni][1] = 0u; }

    load_tile(0);
    asm volatile("cp.async.commit_group;" ::: "memory");
    load_tile(1);
    asm volatile("cp.async.commit_group;" ::: "memory");

    for (int kt = 0; kt < KT; kt++) {
        asm volatile("cp.async.wait_group 1;" ::: "memory");
        __syncthreads();
        if (kt + 2 < KT) load_tile(kt + 2);
        asm volatile("cp.async.commit_group;" ::: "memory");

        const unsigned as = sbase + (kt % 3) * STG;
        const unsigned bs = as + 32768u;
        #pragma unroll
        for (int s = 0; s < 4; s++) {
            unsigned af[4][4];
            #pragma unroll
            for (int mi = 0; mi < 4; mi++) {
                int row = wm + mi * 16 + (lane & 15);
                int ch  = 2 * s + (lane >> 4);
                unsigned addr = as + row * 128 + ((ch ^ (row & 7)) << 4);
                asm volatile("ldmatrix.sync.aligned.m8n8.x4.shared.b16 {%0,%1,%2,%3}, [%4];"
                    : "=r"(af[mi][0]), "=r"(af[mi][1]), "=r"(af[mi][2]), "=r"(af[mi][3])
                    : "r"(addr));
            }
            unsigned bf[8][2];
            #pragma unroll
            for (int nj = 0; nj < 4; nj++) {
                int row = wn + nj * 16 + (lane & 7) + ((lane & 16) >> 1);
                int ch  = 2 * s + ((lane >> 3) & 1);
                unsigned addr = bs + row * 128 + ((ch ^ (row & 7)) << 4);
                asm volatile("ldmatrix.sync.aligned.m8n8.x4.shared.b16 {%0,%1,%2,%3}, [%4];"
                    : "=r"(bf[2 * nj][0]), "=r"(bf[2 * nj][1]),
                      "=r"(bf[2 * nj + 1][0]), "=r"(bf[2 * nj + 1][1])
                    : "r"(addr));
            }
            #pragma unroll
            for (int mi = 0; mi < 4; mi++)
                #pragma unroll
                for (int ni = 0; ni < 8; ni++) {
                    asm volatile(
                        "mma.sync.aligned.m16n8k16.row.col.f16.f16.f16.f16 "
                        "{%0,%1}, {%2,%3,%4,%5}, {%6,%7}, {%0,%1};"
                        : "+r"(acc[mi][ni][0]), "+r"(acc[mi][ni][1])
                        : "r"(af[mi][0]), "r"(af[mi][1]), "r"(af[mi][2]), "r"(af[mi][3]),
                          "r"(bf[ni][0]), "r"(bf[ni][1]));
                }
        }
    }

    const float scale = *scale_p;
    #pragma unroll
    for (int mi = 0; mi < 4; mi++) {
        #pragma unroll
        for (int ni = 0; ni < 8; ni++) {
            int r0 = bm + wm + mi * 16 + (lane >> 2);
            int c0 = bn + wn + ni * 8 + 2 * (lane & 3);
            float bz0 = __ldg(&bias[c0]), bz1 = __ldg(&bias[c0 + 1]);
            float2 a01 = __half22float2(*reinterpret_cast<__half2*>(&acc[mi][ni][0]));
            float2 a23 = __half22float2(*reinterpret_cast<__half2*>(&acc[mi][ni][1]));
            float v0 = fmaxf(fmaf(a01.x, scale, bz0), 0.0f);
            float v1 = fmaxf(fmaf(a01.y, scale, bz1), 0.0f);
            float v2 = fmaxf(fmaf(a23.x, scale, bz0), 0.0f);
            float v3 = fmaxf(fmaf(a23.y, scale, bz1), 0.0f);
            *reinterpret_cast<uint32_t*>(C + (size_t)r0 * Nst + c0)       = pack_h2(v0, v1);
            *reinterpret_cast<uint32_t*>(C + (size_t)(r0 + 8) * Nst + c0) = pack_h2(v2, v3);
        }
    }
}

// ============= FUSED GEMM (layer 3 + actor math): BM=BN=128, 256 threads =============
__global__ void __launch_bounds__(256, 2)
gemm_fused(const __half* __restrict__ A,
           const __half* __restrict__ Bw,
           const float* __restrict__ bias,
           const float* __restrict__ scale_p,
           int K,
           const float* __restrict__ eps,
           float* __restrict__ action,
           float* __restrict__ logp) {
    extern __shared__ char smem[];
    constexpr unsigned STG = 32768u;
    const int tid  = threadIdx.x;
    const int lane = tid & 31;
    const int warp = tid >> 5;
    const int wm = (warp & 3) * 32;
    const int wn = (warp >> 2) * 64;
    const int bm = blockIdx.y * 128;
    const unsigned sbase = (unsigned)__cvta_generic_to_shared(smem);
    const int KT = K >> 6;

    auto load_tile = [&](int c) {
        const int st = c % 3;
        const __half* Ag = A + (size_t)bm * K + c * 64;
        const __half* Bg = Bw + c * 64;
        const unsigned as = sbase + st * STG;
        const unsigned bs = as + 16384u;
        #pragma unroll
        for (int i = 0; i < 4; i++) {
            int idx = tid + i * 256;
            int row = idx >> 3, ch = idx & 7, sw = ch ^ (row & 7);
            asm volatile("cp.async.cg.shared.global [%0], [%1], 16;" ::
                "r"(as + row * 128u + sw * 16u), "l"(Ag + (size_t)row * K + ch * 8));
        }
        #pragma unroll
        for (int i = 0; i < 4; i++) {
            int idx = tid + i * 256;
            int row = idx >> 3, ch = idx & 7, sw = ch ^ (row & 7);
            asm volatile("cp.async.cg.shared.global [%0], [%1], 16;" ::
                "r"(bs + row * 128u + sw * 16u), "l"(Bg + (size_t)row * K + ch * 8));
        }
    };

    uint32_t acc[2][8][2];
    #pragma unroll
    for (int mi = 0; mi < 2; mi++)
        #pragma unroll
        for (int ni = 0; ni < 8; ni++) { acc[mi][ni][0] = 0u; acc[mi][ni][1] = 0u; }

    load_tile(0);
    asm volatile("cp.async.commit_group;" ::: "memory");
    load_tile(1);
    asm volatile("cp.async.commit_group;" ::: "memory");

    for (int kt = 0; kt < KT; kt++) {
        asm volatile("cp.async.wait_group 1;" ::: "memory");
        __syncthreads();
        if (kt + 2 < KT) load_tile(kt + 2);
        asm volatile("cp.async.commit_group;" ::: "memory");

        const unsigned as = sbase + (kt % 3) * STG;
        const unsigned bs = as + 16384u;
        #pragma unroll
        for (int s = 0; s < 4; s++) {
            unsigned af[2][4];
            #pragma unroll
            for (int mi = 0; mi < 2; mi++) {
                int row = wm + mi * 16 + (lane & 15);
                int ch  = 2 * s + (lane >> 4);
                unsigned addr = as + row * 128 + ((ch ^ (row & 7)) << 4);
                asm volatile("ldmatrix.sync.aligned.m8n8.x4.shared.b16 {%0,%1,%2,%3}, [%4];"
                    : "=r"(af[mi][0]), "=r"(af[mi][1]), "=r"(af[mi][2]), "=r"(af[mi][3])
                    : "r"(addr));
            }
            unsigned bf[8][2];
            #pragma unroll
            for (int nj = 0; nj < 4; nj++) {
                int row = wn + nj * 16 + (lane & 7) + ((lane & 16) >> 1);
                int ch  = 2 * s + ((lane >> 3) & 1);
                unsigned addr = bs + row * 128 + ((ch ^ (row & 7)) << 4);
                asm volatile("ldmatrix.sync.aligned.m8n8.x4.shared.b16 {%0,%1,%2,%3}, [%4];"
                    : "=r"(bf[2 * nj][0]), "=r"(bf[2 * nj][1]),
                      "=r"(bf[2 * nj + 1][0]), "=r"(bf[2 * nj + 1][1])
                    : "r"(addr));
            }
            #pragma unroll
            for (int mi = 0; mi < 2; mi++)
                #pragma unroll
                for (int ni = 0; ni < 8; ni++) {
                    asm volatile(
                        "mma.sync.aligned.m16n8k16.row.col.f16.f16.f16.f16 "
                        "{%0,%1}, {%2,%3,%4,%5}, {%6,%7}, {%0,%1};"
                        : "+r"(acc[mi][ni][0]), "+r"(acc[mi][ni][1])
                        : "r"(af[mi][0]), "r"(af[mi][1]), "r"(af[mi][2]), "r"(af[mi][3]),
                          "r"(bf[ni][0]), "r"(bf[ni][1]));
                }
        }
    }

    const float scale = *scale_p;
    // wn=0 warps hold mu (cols 0..63), wn=64 warps hold log_std (cols 64..127).
    asm volatile("cp.async.wait_group 0;" ::: "memory");
    __syncthreads();
    constexpr int LSS = 65;
    float* ls_s  = (float*)smem;               // [128][65]
    float* std_s = ls_s + 128 * LSS;           // [128][65]
    if (wn == 64) {
        #pragma unroll
        for (int mi = 0; mi < 2; mi++) {
            const int rl = wm + mi * 16 + (lane >> 2);
            #pragma unroll
            for (int ni = 0; ni < 8; ni++) {
                const int c = ni * 8 + 2 * (lane & 3);
                float bz0 = __ldg(&bias[64 + c]), bz1 = __ldg(&bias[64 + c + 1]);
                float2 a01 = __half22float2(*reinterpret_cast<__half2*>(&acc[mi][ni][0]));
                float2 a23 = __half22float2(*reinterpret_cast<__half2*>(&acc[mi][ni][1]));
                float l0 = fminf(fmaxf(fmaf(a01.x, scale, bz0), -20.0f), 2.0f);
                float l1 = fminf(fmaxf(fmaf(a01.y, scale, bz1), -20.0f), 2.0f);
                float l2 = fminf(fmaxf(fmaf(a23.x, scale, bz0), -20.0f), 2.0f);
                float l3 = fminf(fmaxf(fmaf(a23.y, scale, bz1), -20.0f), 2.0f);
                ls_s[rl * LSS + c]           = l0;
                ls_s[rl * LSS + c + 1]       = l1;
                ls_s[(rl + 8) * LSS + c]     = l2;
                ls_s[(rl + 8) * LSS + c + 1] = l3;
                std_s[rl * LSS + c]           = expf(l0);
                std_s[rl * LSS + c + 1]       = expf(l1);
                std_s[(rl + 8) * LSS + c]     = expf(l2);
                std_s[(rl + 8) * LSS + c + 1] = expf(l3);
            }
        }
    }
    __syncthreads();
    if (wn == 0) {
        float lp[2][2] = {{0.0f, 0.0f}, {0.0f, 0.0f}};
        #pragma unroll
        for (int mi = 0; mi < 2; mi++) {
            const int rl = wm + mi * 16 + (lane >> 2);
            const int m0 = bm + rl, m1 = m0 + 8;
            #pragma unroll
            for (int ni = 0; ni < 8; ni++) {
                const int c = ni * 8 + 2 * (lane & 3);
                float bz0 = __ldg(&bias[c]), bz1 = __ldg(&bias[c + 1]);
                float2 e0 = *reinterpret_cast<const float2*>(eps + (size_t)m0 * ACT_D + c);
                float2 e1 = *reinterpret_cast<const float2*>(eps + (size_t)m1 * ACT_D + c);
                float2 a01 = __half22float2(*reinterpret_cast<__half2*>(&acc[mi][ni][0]));
                float2 a23 = __half22float2(*reinterpret_cast<__half2*>(&acc[mi][ni][1]));
                float mus[4] = {
                    fmaf(a01.x, scale, bz0), fmaf(a01.y, scale, bz1),
                    fmaf(a23.x, scale, bz0), fmaf(a23.y, scale, bz1)};
                const int rr[4] = {rl, rl, rl + 8, rl + 8};
                const int cc[4] = {c, c + 1, c, c + 1};
                const float ev[4] = {e0.x, e0.y, e1.x, e1.y};
                float av[4];
                #pragma unroll
                for (int e = 0; e < 4; e++) {
                    float sd = std_s[rr[e] * LSS + cc[e]];
                    float ls = ls_s[rr[e] * LSS + cc[e]];
                    float pi = fmaf(sd, ev[e], mus[e]);
                    av[e] = tanhf(pi);
                    float z  = -2.0f * pi;
                    float sp = fmaxf(z, 0.0f) + log1pf(expf(-fabsf(z)));
                    lp[mi][e >> 1] += fmaf(-0.5f * ev[e], ev[e], -ls)
                                    - 0.91893853320467274178f
                                    - 2.0f * (0.69314718055994530942f - pi - sp);
                }
                *reinterpret_cast<float2*>(action + (size_t)m0 * ACT_D + c) = make_float2(av[0], av[1]);
                *reinterpret_cast<float2*>(action + (size_t)m1 * ACT_D + c) = make_float2(av[2], av[3]);
            }
        }
        #pragma unroll
        for (int mi = 0; mi < 2; mi++)
            #pragma unroll
            for (int h = 0; h < 2; h++) {
                lp[mi][h] += __shfl_xor_sync(0xffffffffu, lp[mi][h], 1);
                lp[mi][h] += __shfl_xor_sync(0xffffffffu, lp[mi][h], 2);
            }
        if ((lane & 3) == 0) {
            #pragma unroll
            for (int mi = 0; mi < 2; mi++) {
                const int rl = wm + mi * 16 + (lane >> 2);
                logp[bm + rl]     = lp[mi][0];
                logp[bm + rl + 8] = lp[mi][1];
            }
        }
    }
}

// ---------------- launch ----------------
extern "C" void kernel_launch(void* const* d_in, const int* in_sizes, int n_in,
                              void* d_out, int out_size) {
    const float* obs = (const float*)d_in[0];
    const float* eps = (const float*)d_in[1];
    const float* W1  = (const float*)d_in[2];
    const float* b1  = (const float*)d_in[3];
    const float* W2  = (const float*)d_in[4];
    const float* b2  = (const float*)d_in[5];
    const float* W3  = (const float*)d_in[6];
    const float* b3  = (const float*)d_in[7];
    float* out = (float*)d_out;

    void *xb, *h1, *h2, *w1, *w2, *w3, *b1q, *b2q, *b3q, *sc;
    cudaGetSymbolAddress(&xb,  g_xb);
    cudaGetSymbolAddress(&h1,  g_h1);
    cudaGetSymbolAddress(&h2,  g_h2);
    cudaGetSymbolAddress(&w1,  g_w1);
    cudaGetSymbolAddress(&w2,  g_w2);
    cudaGetSymbolAddress(&w3,  g_w3);
    cudaGetSymbolAddress(&b1q, g_b1q);
    cudaGetSymbolAddress(&b2q, g_b2q);
    cudaGetSymbolAddress(&b3q, g_b3q);
    cudaGetSymbolAddress(&sc,  g_scales);

    const unsigned SM_BIG = 3u * 65536u;   // 192 KB, occ 1
    const unsigned SM_FUS = 3u * 32768u;   // 96 KB,  occ 2
    cudaFuncSetAttribute((const void*)gemm_big,
                         cudaFuncAttributeMaxDynamicSharedMemorySize, SM_BIG);
    cudaFuncSetAttribute((const void*)gemm_fused,
                         cudaFuncAttributeMaxDynamicSharedMemorySize, SM_FUS);

    zero_absmax_kernel<<<1, 32>>>();
    absmax3_kernel<<<208, 256>>>((const float4*)W1, (const float4*)W2, (const float4*)W3);
    prep_kernel<<<1, 1024>>>(b1, b2, b3);
    quant3_kernel<<<208, 256>>>((const float4*)W1, (const float4*)W2, (const float4*)W3);
    cvt_obs4_kernel<<<4096, 256>>>((const float4*)obs, (uint2*)xb, (B_ROWS * OBS_D) / 4);

    // layer 1: [32768,512] @ [1024,512]^T -> relu fp16 (x4096)
    gemm_big<<<dim3(H1_D / 256, B_ROWS / 256), 512, SM_BIG>>>(
        (const __half*)xb, (const __half*)w1, (__half*)h1,
        (const float*)b1q, (const float*)sc + 0, OBS_D, H1_D);

    // layer 2: [32768,1024] @ [1024,1024]^T -> relu fp16 (x4096)
    gemm_big<<<dim3(H2_D / 256, B_ROWS / 256), 512, SM_BIG>>>(
        (const __half*)h1, (const __half*)w2, (__half*)h2,
        (const float*)b2q, (const float*)sc + 1, H1_D, H2_D);

    // layer 3 fused with actor math: action + logp straight to d_out
    gemm_fused<<<dim3(1, B_ROWS / 128), 256, SM_FUS>>>(
        (const __half*)h2, (const __half*)w3,
        (const float*)b3q, (const float*)sc + 2, H2_D,
        eps, out, out + (size_t)B_ROWS * ACT_D);
}

// round 13
// speedup vs baseline: 1.1310x; 1.1310x over previous
#include <cuda_runtime.h>
#include <cuda_fp16.h>
#include <math.h>
#include <stdint.h>

// Problem dims (fixed by the dataset)
#define B_ROWS 32768
#define OBS_D  512
#define H1_D   1024
#define H2_D   1024
#define ACT_D  64
#define OUT3_D (2*ACT_D)   // 128

// Activation rescale: hidden activations (~2e-5) are fp16-subnormal, so store
// h*4096 (exact power of two) and fold 1/4096 into the next layer's scale.
#define HSCALE 4096.0f

// ---------------- device scratch (no allocs allowed) ----------------
__device__ __align__(256) __half g_xb[(size_t)B_ROWS * OBS_D];
__device__ __align__(256) __half g_h1[(size_t)B_ROWS * H1_D];
__device__ __align__(256) __half g_h2[(size_t)B_ROWS * H2_D];
__device__ __align__(256) __half g_w1[H1_D * OBS_D];     // int-valued quant weights (fp16-exact)
__device__ __align__(256) __half g_w2[H2_D * H1_D];
__device__ __align__(256) __half g_w3[OUT3_D * H2_D];
__device__ float g_b1q[H1_D], g_b2q[H2_D], g_b3q[OUT3_D];
__device__ float g_absmax[3];
__device__ float g_scales[3];

__device__ __forceinline__ uint32_t pack_h2(float lo, float hi) {
    uint32_t r;
    asm("cvt.rn.f16x2.f32 %0, %1, %2;" : "=r"(r) : "f"(hi), "f"(lo));
    return r;
}

// ---------------- prep kernels ----------------
__global__ void zero_absmax_kernel() {
    if (threadIdx.x < 3) g_absmax[threadIdx.x] = 0.0f;
}

// blocks [0,64)->W1  [64,192)->W2  [192,208)->W3
__global__ void absmax3_kernel(const float4* __restrict__ W1,
                               const float4* __restrict__ W2,
                               const float4* __restrict__ W3) {
    int b = blockIdx.x;
    const float4* W; int n4, nb, which;
    if (b < 64)       { W = W1; n4 = (H1_D * OBS_D) / 4; nb = 64;  which = 0; }
    else if (b < 192) { W = W2; n4 = (H2_D * H1_D) / 4;  nb = 128; which = 1; b -= 64; }
    else              { W = W3; n4 = (OUT3_D * H2_D) / 4; nb = 16; which = 2; b -= 192; }
    float m = 0.0f;
    for (int i = b * 256 + threadIdx.x; i < n4; i += nb * 256) {
        float4 v = W[i];
        m = fmaxf(m, fmaxf(fmaxf(fabsf(v.x), fabsf(v.y)), fmaxf(fabsf(v.z), fabsf(v.w))));
    }
    #pragma unroll
    for (int off = 16; off; off >>= 1)
        m = fmaxf(m, __shfl_xor_sync(0xffffffffu, m, off));
    if ((threadIdx.x & 31) == 0)
        atomicMax(reinterpret_cast<int*>(&g_absmax[which]), __float_as_int(m));
}

__global__ void prep_kernel(const float* __restrict__ b1,
                            const float* __restrict__ b2,
                            const float* __restrict__ b3) {
    const float s_in = 1.0f / 12000.0f;
    const float ws1 = g_absmax[0] * (1.0f / 127.0f);
    const float ws2 = g_absmax[1] * (1.0f / 127.0f);
    const float ws3 = g_absmax[2] * (1.0f / 127.0f);
    const int t = threadIdx.x;
    if (t == 0) {
        g_scales[0] = s_in * s_in * ws1 * HSCALE;  // layer1 out pre-scaled by 4096
        g_scales[1] = ws2;                          // 4096 in / 4096 out cancel
        g_scales[2] = ws3 / HSCALE;                 // undo input prescale
    }
    const float s1  = s_in * ws1;
    const float sb2 = s1 * ws2;
    const float s2  = s1 * ws2;
    const float sb3 = s2 * ws3;
    // biases for layers 1,2 folded with the 4096 output prescale (ReLU commutes)
    if (t < H1_D)   g_b1q[t] = fminf(fmaxf(rintf(b1[t] / s1),  -128.0f), 127.0f) * s1  * HSCALE;
    if (t < H2_D)   g_b2q[t] = fminf(fmaxf(rintf(b2[t] / sb2), -128.0f), 127.0f) * sb2 * HSCALE;
    if (t < OUT3_D) g_b3q[t] = fminf(fmaxf(rintf(b3[t] / sb3), -128.0f), 127.0f) * sb3;
}

__global__ void quant3_kernel(const float4* __restrict__ W1,
                              const float4* __restrict__ W2,
                              const float4* __restrict__ W3) {
    int b = blockIdx.x;
    const float4* W; uint2* O; int n4, nb, which;
    if (b < 64)       { W = W1; O = (uint2*)g_w1; n4 = (H1_D * OBS_D) / 4; nb = 64;  which = 0; }
    else if (b < 192) { W = W2; O = (uint2*)g_w2; n4 = (H2_D * H1_D) / 4;  nb = 128; which = 1; b -= 64; }
    else              { W = W3; O = (uint2*)g_w3; n4 = (OUT3_D * H2_D) / 4; nb = 16; which = 2; b -= 192; }
    const float inv = 127.0f / g_absmax[which];
    for (int i = b * 256 + threadIdx.x; i < n4; i += nb * 256) {
        float4 v = W[i];
        float q0 = fminf(fmaxf(rintf(v.x * inv), -127.0f), 127.0f);
        float q1 = fminf(fmaxf(rintf(v.y * inv), -127.0f), 127.0f);
        float q2 = fminf(fmaxf(rintf(v.z * inv), -127.0f), 127.0f);
        float q3 = fminf(fmaxf(rintf(v.w * inv), -127.0f), 127.0f);
        uint2 o;
        o.x = pack_h2(q0, q1);
        o.y = pack_h2(q2, q3);
        O[i] = o;
    }
}

__global__ void cvt_obs4_kernel(const float4* __restrict__ src, uint2* __restrict__ dst, int n4) {
    for (int i = blockIdx.x * blockDim.x + threadIdx.x; i < n4; i += gridDim.x * blockDim.x) {
        float4 v = src[i];
        uint2 o;
        o.x = pack_h2(v.x, v.y);
        o.y = pack_h2(v.z, v.w);
        dst[i] = o;
    }
}

// ===== BIG GEMM (layers 1,2): CTA 128x256, 256 thr, warp tile 64x64, occ 2 =====
// C[M,N] = A[M,K] @ Bw[N,K]^T, fp16 in, fp16 acc, 2-stage cp.async (96KB smem).
// Warp layout 2(M) x 4(N). Cuts ldmatrix bytes/MMA by 32% and L2 traffic by 25%
// vs 128x128, while keeping 2 CTAs/SM (which R12 showed is load-bearing).

__global__ void __launch_bounds__(256, 2)
gemm_big(const __half* __restrict__ A,
         const __half* __restrict__ Bw,
         __half* __restrict__ C,
         const float* __restrict__ bias,
         const float* __restrict__ scale_p,
         int K, int Nst) {
    extern __shared__ char smem[];
    constexpr unsigned STG = 49152u;                 // 16KB A + 32KB B per stage
    const int tid  = threadIdx.x;
    const int lane = tid & 31;
    const int warp = tid >> 5;
    const int wm = (warp & 1) * 64;                  // 2 warps in M
    const int wn = (warp >> 1) * 64;                 // 4 warps in N
    const int bm = blockIdx.y * 128;
    const int bn = blockIdx.x * 256;
    const unsigned sbase = (unsigned)__cvta_generic_to_shared(smem);
    const int KT = K >> 6;

    auto load_tile = [&](int c) {
        const int st = c & 1;
        const __half* Ag = A + (size_t)bm * K + c * 64;
        const __half* Bg = Bw + (size_t)bn * K + c * 64;
        const unsigned as = sbase + st * STG;
        const unsigned bs = as + 16384u;
        #pragma unroll
        for (int i = 0; i < 4; i++) {                // A: 128 rows x 8 x 16B
            int idx = tid + i * 256;
            int row = idx >> 3, ch = idx & 7, sw = ch ^ (row & 7);
            asm volatile("cp.async.cg.shared.global [%0], [%1], 16;" ::
                "r"(as + row * 128u + sw * 16u), "l"(Ag + (size_t)row * K + ch * 8));
        }
        #pragma unroll
        for (int i = 0; i < 8; i++) {                // B: 256 rows x 8 x 16B
            int idx = tid + i * 256;
            int row = idx >> 3, ch = idx & 7, sw = ch ^ (row & 7);
            asm volatile("cp.async.cg.shared.global [%0], [%1], 16;" ::
                "r"(bs + row * 128u + sw * 16u), "l"(Bg + (size_t)row * K + ch * 8));
        }
    };

    // fp16 accumulators: warp tile 64x64 = 4 (mi) x 8 (ni) x 2 b32 regs
    uint32_t acc[4][8][2];
    #pragma unroll
    for (int mi = 0; mi < 4; mi++)
        #pragma unroll
        for (int ni = 0; ni < 8; ni++) { acc[mi][ni][0] = 0u; acc[mi][ni][1] = 0u; }

    load_tile(0);
    asm volatile("cp.async.commit_group;" ::: "memory");

    for (int kt = 0; kt < KT; kt++) {
        if (kt + 1 < KT) {                           // prefetch into the other stage
            load_tile(kt + 1);
            asm volatile("cp.async.commit_group;" ::: "memory");
            asm volatile("cp.async.wait_group 1;" ::: "memory");
        } else {
            asm volatile("cp.async.wait_group 0;" ::: "memory");
        }
        __syncthreads();                             // chunk kt visible to all warps

        const unsigned as = sbase + (kt & 1) * STG;
        const unsigned bs = as + 16384u;
        #pragma unroll
        for (int s = 0; s < 4; s++) {
            unsigned af[4][4];
            #pragma unroll
            for (int mi = 0; mi < 4; mi++) {
                int row = wm + mi * 16 + (lane & 15);
                int ch  = 2 * s + (lane >> 4);
                unsigned addr = as + row * 128 + ((ch ^ (row & 7)) << 4);
                asm volatile("ldmatrix.sync.aligned.m8n8.x4.shared.b16 {%0,%1,%2,%3}, [%4];"
                    : "=r"(af[mi][0]), "=r"(af[mi][1]), "=r"(af[mi][2]), "=r"(af[mi][3])
                    : "r"(addr));
            }
            unsigned bf[8][2];
            #pragma unroll
            for (int nj = 0; nj < 4; nj++) {
                int row = wn + nj * 16 + (lane & 7) + ((lane & 16) >> 1);
                int ch  = 2 * s + ((lane >> 3) & 1);
                unsigned addr = bs + row * 128 + ((ch ^ (row & 7)) << 4);
                asm volatile("ldmatrix.sync.aligned.m8n8.x4.shared.b16 {%0,%1,%2,%3}, [%4];"
                    : "=r"(bf[2 * nj][0]), "=r"(bf[2 * nj][1]),
                      "=r"(bf[2 * nj + 1][0]), "=r"(bf[2 * nj + 1][1])
                    : "r"(addr));
            }
            #pragma unroll
            for (int mi = 0; mi < 4; mi++)
                #pragma unroll
                for (int ni = 0; ni < 8; ni++) {
                    asm volatile(
                        "mma.sync.aligned.m16n8k16.row.col.f16.f16.f16.f16 "
                        "{%0,%1}, {%2,%3,%4,%5}, {%6,%7}, {%0,%1};"
                        : "+r"(acc[mi][ni][0]), "+r"(acc[mi][ni][1])
                        : "r"(af[mi][0]), "r"(af[mi][1]), "r"(af[mi][2]), "r"(af[mi][3]),
                          "r"(bf[ni][0]), "r"(bf[ni][1]));
                }
        }
        __syncthreads();                             // stage reusable for next prefetch
    }

    const float scale = *scale_p;
    #pragma unroll
    for (int mi = 0; mi < 4; mi++) {
        #pragma unroll
        for (int ni = 0; ni < 8; ni++) {
            int r0 = bm + wm + mi * 16 + (lane >> 2);
            int c0 = bn + wn + ni * 8 + 2 * (lane & 3);
            float bz0 = __ldg(&bias[c0]), bz1 = __ldg(&bias[c0 + 1]);
            float2 a01 = __half22float2(*reinterpret_cast<__half2*>(&acc[mi][ni][0]));
            float2 a23 = __half22float2(*reinterpret_cast<__half2*>(&acc[mi][ni][1]));
            float v0 = fmaxf(fmaf(a01.x, scale, bz0), 0.0f);
            float v1 = fmaxf(fmaf(a01.y, scale, bz1), 0.0f);
            float v2 = fmaxf(fmaf(a23.x, scale, bz0), 0.0f);
            float v3 = fmaxf(fmaf(a23.y, scale, bz1), 0.0f);
            *reinterpret_cast<uint32_t*>(C + (size_t)r0 * Nst + c0)       = pack_h2(v0, v1);
            *reinterpret_cast<uint32_t*>(C + (size_t)(r0 + 8) * Nst + c0) = pack_h2(v2, v3);
        }
    }
}

// ===== FUSED GEMM (layer 3 + actor math): BM=BN=128, 256 threads, occ 2 =====
__global__ void __launch_bounds__(256, 2)
gemm_fused(const __half* __restrict__ A,
           const __half* __restrict__ Bw,
           const float* __restrict__ bias,
           const float* __restrict__ scale_p,
           int K,
           const float* __restrict__ eps,
           float* __restrict__ action,
           float* __restrict__ logp) {
    extern __shared__ char smem[];
    constexpr unsigned STG = 32768u;
    const int tid  = threadIdx.x;
    const int lane = tid & 31;
    const int warp = tid >> 5;
    const int wm = (warp & 3) * 32;
    const int wn = (warp >> 2) * 64;
    const int bm = blockIdx.y * 128;
    const unsigned sbase = (unsigned)__cvta_generic_to_shared(smem);
    const int KT = K >> 6;

    auto load_tile = [&](int c) {
        const int st = c % 3;
        const __half* Ag = A + (size_t)bm * K + c * 64;
        const __half* Bg = Bw + c * 64;
        const unsigned as = sbase + st * STG;
        const unsigned bs = as + 16384u;
        #pragma unroll
        for (int i = 0; i < 4; i++) {
            int idx = tid + i * 256;
            int row = idx >> 3, ch = idx & 7, sw = ch ^ (row & 7);
            asm volatile("cp.async.cg.shared.global [%0], [%1], 16;" ::
                "r"(as + row * 128u + sw * 16u), "l"(Ag + (size_t)row * K + ch * 8));
        }
        #pragma unroll
        for (int i = 0; i < 4; i++) {
            int idx = tid + i * 256;
            int row = idx >> 3, ch = idx & 7, sw = ch ^ (row & 7);
            asm volatile("cp.async.cg.shared.global [%0], [%1], 16;" ::
                "r"(bs + row * 128u + sw * 16u), "l"(Bg + (size_t)row * K + ch * 8));
        }
    };

    uint32_t acc[2][8][2];
    #pragma unroll
    for (int mi = 0; mi < 2; mi++)
        #pragma unroll
        for (int ni = 0; ni < 8; ni++) { acc[mi][ni][0] = 0u; acc[mi][ni][1] = 0u; }

    load_tile(0);
    asm volatile("cp.async.commit_group;" ::: "memory");
    load_tile(1);
    asm volatile("cp.async.commit_group;" ::: "memory");

    for (int kt = 0; kt < KT; kt++) {
        asm volatile("cp.async.wait_group 1;" ::: "memory");
        __syncthreads();
        if (kt + 2 < KT) load_tile(kt + 2);
        asm volatile("cp.async.commit_group;" ::: "memory");

        const unsigned as = sbase + (kt % 3) * STG;
        const unsigned bs = as + 16384u;
        #pragma unroll
        for (int s = 0; s < 4; s++) {
            unsigned af[2][4];
            #pragma unroll
            for (int mi = 0; mi < 2; mi++) {
                int row = wm + mi * 16 + (lane & 15);
                int ch  = 2 * s + (lane >> 4);
                unsigned addr = as + row * 128 + ((ch ^ (row & 7)) << 4);
                asm volatile("ldmatrix.sync.aligned.m8n8.x4.shared.b16 {%0,%1,%2,%3}, [%4];"
                    : "=r"(af[mi][0]), "=r"(af[mi][1]), "=r"(af[mi][2]), "=r"(af[mi][3])
                    : "r"(addr));
            }
            unsigned bf[8][2];
            #pragma unroll
            for (int nj = 0; nj < 4; nj++) {
                int row = wn + nj * 16 + (lane & 7) + ((lane & 16) >> 1);
                int ch  = 2 * s + ((lane >> 3) & 1);
                unsigned addr = bs + row * 128 + ((ch ^ (row & 7)) << 4);
                asm volatile("ldmatrix.sync.aligned.m8n8.x4.shared.b16 {%0,%1,%2,%3}, [%4];"
                    : "=r"(bf[2 * nj][0]), "=r"(bf[2 * nj][1]),
                      "=r"(bf[2 * nj + 1][0]), "=r"(bf[2 * nj + 1][1])
                    : "r"(addr));
            }
            #pragma unroll
            for (int mi = 0; mi < 2; mi++)
                #pragma unroll
                for (int ni = 0; ni < 8; ni++) {
                    asm volatile(
                        "mma.sync.aligned.m16n8k16.row.col.f16.f16.f16.f16 "
                        "{%0,%1}, {%2,%3,%4,%5}, {%6,%7}, {%0,%1};"
                        : "+r"(acc[mi][ni][0]), "+r"(acc[mi][ni][1])
                        : "r"(af[mi][0]), "r"(af[mi][1]), "r"(af[mi][2]), "r"(af[mi][3]),
                          "r"(bf[ni][0]), "r"(bf[ni][1]));
                }
        }
    }

    const float scale = *scale_p;
    // wn=0 warps hold mu (cols 0..63), wn=64 warps hold log_std (cols 64..127).
    asm volatile("cp.async.wait_group 0;" ::: "memory");
    __syncthreads();
    constexpr int LSS = 65;
    float* ls_s  = (float*)smem;               // [128][65]
    float* std_s = ls_s + 128 * LSS;           // [128][65]
    if (wn == 64) {
        #pragma unroll
        for (int mi = 0; mi < 2; mi++) {
            const int rl = wm + mi * 16 + (lane >> 2);
            #pragma unroll
            for (int ni = 0; ni < 8; ni++) {
                const int c = ni * 8 + 2 * (lane & 3);
                float bz0 = __ldg(&bias[64 + c]), bz1 = __ldg(&bias[64 + c + 1]);
                float2 a01 = __half22float2(*reinterpret_cast<__half2*>(&acc[mi][ni][0]));
                float2 a23 = __half22float2(*reinterpret_cast<__half2*>(&acc[mi][ni][1]));
                float l0 = fminf(fmaxf(fmaf(a01.x, scale, bz0), -20.0f), 2.0f);
                float l1 = fminf(fmaxf(fmaf(a01.y, scale, bz1), -20.0f), 2.0f);
                float l2 = fminf(fmaxf(fmaf(a23.x, scale, bz0), -20.0f), 2.0f);
                float l3 = fminf(fmaxf(fmaf(a23.y, scale, bz1), -20.0f), 2.0f);
                ls_s[rl * LSS + c]           = l0;
                ls_s[rl * LSS + c + 1]       = l1;
                ls_s[(rl + 8) * LSS + c]     = l2;
                ls_s[(rl + 8) * LSS + c + 1] = l3;
                std_s[rl * LSS + c]           = expf(l0);
                std_s[rl * LSS + c + 1]       = expf(l1);
                std_s[(rl + 8) * LSS + c]     = expf(l2);
                std_s[(rl + 8) * LSS + c + 1] = expf(l3);
            }
        }
    }
    __syncthreads();
    if (wn == 0) {
        float lp[2][2] = {{0.0f, 0.0f}, {0.0f, 0.0f}};
        #pragma unroll
        for (int mi = 0; mi < 2; mi++) {
            const int rl = wm + mi * 16 + (lane >> 2);
            const int m0 = bm + rl, m1 = m0 + 8;
            #pragma unroll
            for (int ni = 0; ni < 8; ni++) {
                const int c = ni * 8 + 2 * (lane & 3);
                float bz0 = __ldg(&bias[c]), bz1 = __ldg(&bias[c + 1]);
                float2 e0 = *reinterpret_cast<const float2*>(eps + (size_t)m0 * ACT_D + c);
                float2 e1 = *reinterpret_cast<const float2*>(eps + (size_t)m1 * ACT_D + c);
                float2 a01 = __half22float2(*reinterpret_cast<__half2*>(&acc[mi][ni][0]));
                float2 a23 = __half22float2(*reinterpret_cast<__half2*>(&acc[mi][ni][1]));
                float mus[4] = {
                    fmaf(a01.x, scale, bz0), fmaf(a01.y, scale, bz1),
                    fmaf(a23.x, scale, bz0), fmaf(a23.y, scale, bz1)};
                const int rr[4] = {rl, rl, rl + 8, rl + 8};
                const int cc[4] = {c, c + 1, c, c + 1};
                const float ev[4] = {e0.x, e0.y, e1.x, e1.y};
                float av[4];
                #pragma unroll
                for (int e = 0; e < 4; e++) {
                    float sd = std_s[rr[e] * LSS + cc[e]];
                    float ls = ls_s[rr[e] * LSS + cc[e]];
                    float pi = fmaf(sd, ev[e], mus[e]);
                    av[e] = tanhf(pi);
                    float z  = -2.0f * pi;
                    float sp = fmaxf(z, 0.0f) + log1pf(expf(-fabsf(z)));
                    lp[mi][e >> 1] += fmaf(-0.5f * ev[e], ev[e], -ls)
                                    - 0.91893853320467274178f
                                    - 2.0f * (0.69314718055994530942f - pi - sp);
                }
                *reinterpret_cast<float2*>(action + (size_t)m0 * ACT_D + c) = make_float2(av[0], av[1]);
                *reinterpret_cast<float2*>(action + (size_t)m1 * ACT_D + c) = make_float2(av[2], av[3]);
            }
        }
        #pragma unroll
        for (int mi = 0; mi < 2; mi++)
            #pragma unroll
            for (int h = 0; h < 2; h++) {
                lp[mi][h] += __shfl_xor_sync(0xffffffffu, lp[mi][h], 1);
                lp[mi][h] += __shfl_xor_sync(0xffffffffu, lp[mi][h], 2);
            }
        if ((lane & 3) == 0) {
            #pragma unroll
            for (int mi = 0; mi < 2; mi++) {
                const int rl = wm + mi * 16 + (lane >> 2);
                logp[bm + rl]     = lp[mi][0];
                logp[bm + rl + 8] = lp[mi][1];
            }
        }
    }
}

// ---------------- launch ----------------
extern "C" void kernel_launch(void* const* d_in, const int* in_sizes, int n_in,
                              void* d_out, int out_size) {
    const float* obs = (const float*)d_in[0];
    const float* eps = (const float*)d_in[1];
    const float* W1  = (const float*)d_in[2];
    const float* b1  = (const float*)d_in[3];
    const float* W2  = (const float*)d_in[4];
    const float* b2  = (const float*)d_in[5];
    const float* W3  = (const float*)d_in[6];
    const float* b3  = (const float*)d_in[7];
    float* out = (float*)d_out;

    void *xb, *h1, *h2, *w1, *w2, *w3, *b1q, *b2q, *b3q, *sc;
    cudaGetSymbolAddress(&xb,  g_xb);
    cudaGetSymbolAddress(&h1,  g_h1);
    cudaGetSymbolAddress(&h2,  g_h2);
    cudaGetSymbolAddress(&w1,  g_w1);
    cudaGetSymbolAddress(&w2,  g_w2);
    cudaGetSymbolAddress(&w3,  g_w3);
    cudaGetSymbolAddress(&b1q, g_b1q);
    cudaGetSymbolAddress(&b2q, g_b2q);
    cudaGetSymbolAddress(&b3q, g_b3q);
    cudaGetSymbolAddress(&sc,  g_scales);

    const unsigned SM_BIG = 2u * 49152u;   // 96 KB, 2-stage -> occ 2
    const unsigned SM_FUS = 3u * 32768u;   // 96 KB, 3-stage -> occ 2
    cudaFuncSetAttribute((const void*)gemm_big,
                         cudaFuncAttributeMaxDynamicSharedMemorySize, SM_BIG);
    cudaFuncSetAttribute((const void*)gemm_fused,
                         cudaFuncAttributeMaxDynamicSharedMemorySize, SM_FUS);

    zero_absmax_kernel<<<1, 32>>>();
    absmax3_kernel<<<208, 256>>>((const float4*)W1, (const float4*)W2, (const float4*)W3);
    prep_kernel<<<1, 1024>>>(b1, b2, b3);
    quant3_kernel<<<208, 256>>>((const float4*)W1, (const float4*)W2, (const float4*)W3);
    cvt_obs4_kernel<<<4096, 256>>>((const float4*)obs, (uint2*)xb, (B_ROWS * OBS_D) / 4);

    // layer 1: [32768,512] @ [1024,512]^T -> relu fp16 (x4096)
    gemm_big<<<dim3(H1_D / 256, B_ROWS / 128), 256, SM_BIG>>>(
        (const __half*)xb, (const __half*)w1, (__half*)h1,
        (const float*)b1q, (const float*)sc + 0, OBS_D, H1_D);

    // layer 2: [32768,1024] @ [1024,1024]^T -> relu fp16 (x4096)
    gemm_big<<<dim3(H2_D / 256, B_ROWS / 128), 256, SM_BIG>>>(
        (const __half*)h1, (const __half*)w2, (__half*)h2,
        (const float*)b2q, (const float*)sc + 1, H1_D, H2_D);

    // layer 3 fused with actor math: action + logp straight to d_out
    gemm_fused<<<dim3(1, B_ROWS / 128), 256, SM_FUS>>>(
        (const __half*)h2, (const __half*)w3,
        (const float*)b3q, (const float*)sc + 2, H2_D,
        eps, out, out + (size_t)B_ROWS * ACT_D);
}

// round 14
// speedup vs baseline: 1.3083x; 1.1568x over previous
#include <cuda_runtime.h>
#include <cuda_fp16.h>
#include <math.h>
#include <stdint.h>

// Problem dims (fixed by the dataset)
#define B_ROWS 32768
#define OBS_D  512
#define H1_D   1024
#define H2_D   1024
#define ACT_D  64
#define OUT3_D 128

// Activation rescale: hidden activations (~2e-5) are fp16-subnormal, so store
// h*4096 (exact power of two) and fold 1/4096 into the next layer's scale.
#define HSCALE 4096.0f

// ---------------- device scratch (no allocs allowed) ----------------
// All tensor buffers live in PACKED TILE LAYOUT:
//   A-tiles: 16 KB blocks = 128 rows x 64 cols fp16, XOR-8 swizzled rows of 128B.
//            block index = (m>>7)*KT + (k>>6), KT = K/64.
//   B-tiles: BN*128-byte blocks = BN rows x 64 cols, same swizzle.
// A bulk copy of one block reproduces exactly the SMEM image the MMA loop wants.
__device__ __align__(256) __half g_xb[(size_t)B_ROWS * OBS_D];
__device__ __align__(256) __half g_h1[(size_t)B_ROWS * H1_D];
__device__ __align__(256) __half g_h2[(size_t)B_ROWS * H2_D];
__device__ __align__(256) __half g_w1[H1_D * OBS_D];
__device__ __align__(256) __half g_w2[H2_D * H1_D];
__device__ __align__(256) __half g_w3[OUT3_D * H2_D];
__device__ float g_b1q[H1_D], g_b2q[H2_D], g_b3q[OUT3_D];
__device__ float g_absmax[3];
__device__ float g_scales[3];

__device__ __forceinline__ uint32_t pack_h2(float lo, float hi) {
    uint32_t r;
    asm("cvt.rn.f16x2.f32 %0, %1, %2;" : "=r"(r) : "f"(hi), "f"(lo));
    return r;
}

// byte offset of element (m, k) in packed A layout with KT k-chunks
__device__ __forceinline__ size_t packA_off(int m, int k, int KT) {
    int blk = (m >> 7) * KT + (k >> 6);
    int row = m & 127;
    int ch  = (k >> 3) & 7;
    return (size_t)blk * 16384 + row * 128 + ((ch ^ (row & 7)) << 4) + (k & 7) * 2;
}

// ---------------- mbarrier / bulk-copy helpers (plain sm_90+ PTX) ----------------
__device__ __forceinline__ void mbar_init(unsigned a, unsigned cnt) {
    asm volatile("mbarrier.init.shared.b64 [%0], %1;" :: "r"(a), "r"(cnt) : "memory");
}
__device__ __forceinline__ void mbar_expect(unsigned a, unsigned bytes) {
    asm volatile("mbarrier.arrive.expect_tx.shared.b64 _, [%0], %1;"
                 :: "r"(a), "r"(bytes) : "memory");
}
__device__ __forceinline__ void bulk_g2s(unsigned dst, const void* src, unsigned bytes,
                                         unsigned mbar) {
    asm volatile(
        "cp.async.bulk.shared::cluster.global.mbarrier::complete_tx::bytes [%0], [%1], %2, [%3];"
        :: "r"(dst), "l"(src), "r"(bytes), "r"(mbar) : "memory");
}
__device__ __forceinline__ void mbar_wait(unsigned a, unsigned parity) {
    asm volatile(
        "{\n\t.reg .pred P;\n"
        "W%=:\n\t"
        "mbarrier.try_wait.parity.acquire.cta.shared::cta.b64 P, [%0], %1;\n\t"
        "@P bra D%=;\n\t"
        "bra W%=;\n"
        "D%=:\n\t}"
        :: "r"(a), "r"(parity) : "memory");
}

// ---------------- prep kernels ----------------
__global__ void zero_absmax_kernel() {
    if (threadIdx.x < 3) g_absmax[threadIdx.x] = 0.0f;
}

// blocks [0,64)->W1  [64,192)->W2  [192,208)->W3
__global__ void absmax3_kernel(const float4* __restrict__ W1,
                               const float4* __restrict__ W2,
                               const float4* __restrict__ W3) {
    int b = blockIdx.x;
    const float4* W; int n4, nb, which;
    if (b < 64)       { W = W1; n4 = (H1_D * OBS_D) / 4; nb = 64;  which = 0; }
    else if (b < 192) { W = W2; n4 = (H2_D * H1_D) / 4;  nb = 128; which = 1; b -= 64; }
    else              { W = W3; n4 = (OUT3_D * H2_D) / 4; nb = 16; which = 2; b -= 192; }
    float m = 0.0f;
    for (int i = b * 256 + threadIdx.x; i < n4; i += nb * 256) {
        float4 v = W[i];
        m = fmaxf(m, fmaxf(fmaxf(fabsf(v.x), fabsf(v.y)), fmaxf(fabsf(v.z), fabsf(v.w))));
    }
    #pragma unroll
    for (int off = 16; off; off >>= 1)
        m = fmaxf(m, __shfl_xor_sync(0xffffffffu, m, off));
    if ((threadIdx.x & 31) == 0)
        atomicMax(reinterpret_cast<int*>(&g_absmax[which]), __float_as_int(m));
}

__global__ void prep_kernel(const float* __restrict__ b1,
                            const float* __restrict__ b2,
                            const float* __restrict__ b3) {
    const float s_in = 1.0f / 12000.0f;
    const float ws1 = g_absmax[0] * (1.0f / 127.0f);
    const float ws2 = g_absmax[1] * (1.0f / 127.0f);
    const float ws3 = g_absmax[2] * (1.0f / 127.0f);
    const int t = threadIdx.x;
    if (t == 0) {
        g_scales[0] = s_in * s_in * ws1 * HSCALE;  // layer1 out pre-scaled by 4096
        g_scales[1] = ws2;                          // 4096 in / 4096 out cancel
        g_scales[2] = ws3 / HSCALE;                 // undo input prescale
    }
    const float s1  = s_in * ws1;
    const float sb2 = s1 * ws2;
    const float s2  = s1 * ws2;
    const float sb3 = s2 * ws3;
    if (t < H1_D)   g_b1q[t] = fminf(fmaxf(rintf(b1[t] / s1),  -128.0f), 127.0f) * s1  * HSCALE;
    if (t < H2_D)   g_b2q[t] = fminf(fmaxf(rintf(b2[t] / sb2), -128.0f), 127.0f) * sb2 * HSCALE;
    if (t < OUT3_D) g_b3q[t] = fminf(fmaxf(rintf(b3[t] / sb3), -128.0f), 127.0f) * sb3;
}

// Quantize weights AND write them in packed swizzled B-tile layout.
// blocks [0,256)->W1  [256,768)->W2  [768,832)->W3
__global__ void quant3_pack_kernel(const float* __restrict__ W1,
                                   const float* __restrict__ W2,
                                   const float* __restrict__ W3) {
    int b = blockIdx.x;
    const float* W; char* O; int Kw, BNm1, BNlog, KT, which;
    if (b < 256)      { W = W1; O = (char*)g_w1; Kw = 512;  BNm1 = 255; BNlog = 8; KT = 8;  which = 0; }
    else if (b < 768) { W = W2; O = (char*)g_w2; Kw = 1024; BNm1 = 255; BNlog = 8; KT = 16; which = 1; b -= 256; }
    else              { W = W3; O = (char*)g_w3; Kw = 1024; BNm1 = 127; BNlog = 7; KT = 16; which = 2; b -= 768; }
    const float inv = 127.0f / g_absmax[which];
    const int id = b * 256 + threadIdx.x;        // one 16B output chunk (8 weights)
    const int kc = Kw >> 3;                       // 16B chunks per row (64 or 128)
    const int n = id / kc, c8 = id % kc;          // kc is 64 or 128 -> compiler uses shifts
    const int k = c8 << 3;
    const float4* s = reinterpret_cast<const float4*>(W + (size_t)n * Kw + k);
    float4 v0 = s[0], v1 = s[1];
    float q[8] = {v0.x, v0.y, v0.z, v0.w, v1.x, v1.y, v1.z, v1.w};
    #pragma unroll
    for (int e = 0; e < 8; e++)
        q[e] = fminf(fmaxf(rintf(q[e] * inv), -127.0f), 127.0f);
    uint4 o;
    o.x = pack_h2(q[0], q[1]); o.y = pack_h2(q[2], q[3]);
    o.z = pack_h2(q[4], q[5]); o.w = pack_h2(q[6], q[7]);
    const int blk = (n >> BNlog) * KT + (k >> 6);
    const int row = n & BNm1;
    const int ch  = c8 & 7;
    size_t off = (size_t)blk * ((size_t)(BNm1 + 1) * 128) + row * 128 + ((ch ^ (row & 7)) << 4);
    *reinterpret_cast<uint4*>(O + off) = o;
}

// obs fp32 -> packed swizzled A-tile fp16 layout (KT = 8)
__global__ void cvt_obs_pack_kernel(const float* __restrict__ src, char* __restrict__ dst) {
    const int id = blockIdx.x * 256 + threadIdx.x;   // one 16B chunk
    const int m = id >> 6, c8 = id & 63, k = c8 << 3;
    const float4* s = reinterpret_cast<const float4*>(src + (size_t)m * OBS_D + k);
    float4 v0 = s[0], v1 = s[1];
    uint4 o;
    o.x = pack_h2(v0.x, v0.y); o.y = pack_h2(v0.z, v0.w);
    o.z = pack_h2(v1.x, v1.y); o.w = pack_h2(v1.z, v1.w);
    *reinterpret_cast<uint4*>(dst + packA_off(m, k, 8)) = o;
}

// ===== BIG GEMM (layers 1,2): CTA 128x256, 256 thr, warp tile 64x64, occ 2 =====
// Tiles arrive via ONE cp.async.bulk per operand per stage (issued by tid 0),
// completing on an mbarrier -> zero per-thread load-issue cost.
// Output written in packed A-layout for the next consumer (KTC chunks).

__global__ void __launch_bounds__(256, 2)
gemm_big(const char* __restrict__ Apk,   // packed A tiles (16 KB blocks, KT per row-block)
         const char* __restrict__ Bpk,   // packed B tiles (32 KB blocks, KT per col-block)
         char* __restrict__ Cpk,         // packed output (A layout, KTC chunks)
         const float* __restrict__ bias,
         const float* __restrict__ scale_p,
         int KT, int KTC) {
    extern __shared__ char smem[];
    __shared__ __align__(8) unsigned long long mbar_s[2];
    constexpr unsigned STG = 49152u;                 // 16KB A + 32KB B per stage
    const int tid  = threadIdx.x;
    const int lane = tid & 31;
    const int warp = tid >> 5;
    const int wm = (warp & 1) * 64;                  // 2 warps in M
    const int wn = (warp >> 1) * 64;                 // 4 warps in N
    const int bmb = blockIdx.y;                      // 128-row block
    const int bnb = blockIdx.x;                      // 256-col block
    const unsigned sbase = (unsigned)__cvta_generic_to_shared(smem);
    const unsigned mb0 = (unsigned)__cvta_generic_to_shared(&mbar_s[0]);

    if (tid == 0) {
        mbar_init(mb0, 1);
        mbar_init(mb0 + 8, 1);
        asm volatile("fence.proxy.async.shared::cta;" ::: "memory");
    }
    __syncthreads();

    auto issue = [&](int c) {                        // tid 0 only
        const unsigned st = c & 1;
        const unsigned mb = mb0 + st * 8;
        mbar_expect(mb, 49152u);
        bulk_g2s(sbase + st * STG,          Apk + ((size_t)bmb * KT + c) * 16384, 16384u, mb);
        bulk_g2s(sbase + st * STG + 16384u, Bpk + ((size_t)bnb * KT + c) * 32768, 32768u, mb);
    };
    if (tid == 0) { issue(0); issue(1); }

    uint32_t acc[4][8][2];
    #pragma unroll
    for (int mi = 0; mi < 4; mi++)
        #pragma unroll
        for (int ni = 0; ni < 8; ni++) { acc[mi][ni][0] = 0u; acc[mi][ni][1] = 0u; }

    for (int kt = 0; kt < KT; kt++) {
        mbar_wait(mb0 + (kt & 1) * 8, (kt >> 1) & 1);

        const unsigned as = sbase + (kt & 1) * STG;
        const unsigned bs = as + 16384u;
        #pragma unroll
        for (int s = 0; s < 4; s++) {
            unsigned af[4][4];
            #pragma unroll
            for (int mi = 0; mi < 4; mi++) {
                int row = wm + mi * 16 + (lane & 15);
                int ch  = 2 * s + (lane >> 4);
                unsigned addr = as + row * 128 + ((ch ^ (row & 7)) << 4);
                asm volatile("ldmatrix.sync.aligned.m8n8.x4.shared.b16 {%0,%1,%2,%3}, [%4];"
                    : "=r"(af[mi][0]), "=r"(af[mi][1]), "=r"(af[mi][2]), "=r"(af[mi][3])
                    : "r"(addr));
            }
            unsigned bf[8][2];
            #pragma unroll
            for (int nj = 0; nj < 4; nj++) {
                int row = wn + nj * 16 + (lane & 7) + ((lane & 16) >> 1);
                int ch  = 2 * s + ((lane >> 3) & 1);
                unsigned addr = bs + row * 128 + ((ch ^ (row & 7)) << 4);
                asm volatile("ldmatrix.sync.aligned.m8n8.x4.shared.b16 {%0,%1,%2,%3}, [%4];"
                    : "=r"(bf[2 * nj][0]), "=r"(bf[2 * nj][1]),
                      "=r"(bf[2 * nj + 1][0]), "=r"(bf[2 * nj + 1][1])
                    : "r"(addr));
            }
            #pragma unroll
            for (int mi = 0; mi < 4; mi++)
                #pragma unroll
                for (int ni = 0; ni < 8; ni++) {
                    asm volatile(
                        "mma.sync.aligned.m16n8k16.row.col.f16.f16.f16.f16 "
                        "{%0,%1}, {%2,%3,%4,%5}, {%6,%7}, {%0,%1};"
                        : "+r"(acc[mi][ni][0]), "+r"(acc[mi][ni][1])
                        : "r"(af[mi][0]), "r"(af[mi][1]), "r"(af[mi][2]), "r"(af[mi][3]),
                          "r"(bf[ni][0]), "r"(bf[ni][1]));
                }
        }
        __syncthreads();                             // all warps done reading stage
        if (tid == 0 && kt + 2 < KT) issue(kt + 2);
    }

    const float scale = *scale_p;
    #pragma unroll
    for (int mi = 0; mi < 4; mi++) {
        #pragma unroll
        for (int ni = 0; ni < 8; ni++) {
            int r0 = bmb * 128 + wm + mi * 16 + (lane >> 2);
            int c0 = bnb * 256 + wn + ni * 8 + 2 * (lane & 3);
            float bz0 = __ldg(&bias[c0]), bz1 = __ldg(&bias[c0 + 1]);
            float2 a01 = __half22float2(*reinterpret_cast<__half2*>(&acc[mi][ni][0]));
            float2 a23 = __half22float2(*reinterpret_cast<__half2*>(&acc[mi][ni][1]));
            float v0 = fmaxf(fmaf(a01.x, scale, bz0), 0.0f);
            float v1 = fmaxf(fmaf(a01.y, scale, bz1), 0.0f);
            float v2 = fmaxf(fmaf(a23.x, scale, bz0), 0.0f);
            float v3 = fmaxf(fmaf(a23.y, scale, bz1), 0.0f);
            *reinterpret_cast<uint32_t*>(Cpk + packA_off(r0,     c0, KTC)) = pack_h2(v0, v1);
            *reinterpret_cast<uint32_t*>(Cpk + packA_off(r0 + 8, c0, KTC)) = pack_h2(v2, v3);
        }
    }
}

// ===== FUSED GEMM (layer 3 + actor math): BM=128, BN=128, 256 threads, occ 2 =====
// 3-stage bulk pipeline (A 16KB + B 16KB per stage).
__global__ void __launch_bounds__(256, 2)
gemm_fused(const char* __restrict__ Apk,   // packed h2 (KT=16)
           const char* __restrict__ Bpk,   // packed w3 tiles (16 KB each, indexed by kt)
           const float* __restrict__ bias,
           const float* __restrict__ scale_p,
           const float* __restrict__ eps,
           float* __restrict__ action,
           float* __restrict__ logp) {
    extern __shared__ char smem[];
    __shared__ __align__(8) unsigned long long mbar_s[3];
    constexpr unsigned STG = 32768u;
    constexpr int KT = 16;
    const int tid  = threadIdx.x;
    const int lane = tid & 31;
    const int warp = tid >> 5;
    const int wm = (warp & 3) * 32;
    const int wn = (warp >> 2) * 64;
    const int bmb = blockIdx.y;
    const int bm = bmb * 128;
    const unsigned sbase = (unsigned)__cvta_generic_to_shared(smem);
    const unsigned mb0 = (unsigned)__cvta_generic_to_shared(&mbar_s[0]);

    if (tid == 0) {
        mbar_init(mb0, 1); mbar_init(mb0 + 8, 1); mbar_init(mb0 + 16, 1);
        asm volatile("fence.proxy.async.shared::cta;" ::: "memory");
    }
    __syncthreads();

    auto issue = [&](int c) {
        const unsigned st = c % 3;
        const unsigned mb = mb0 + st * 8;
        mbar_expect(mb, 32768u);
        bulk_g2s(sbase + st * STG,          Apk + ((size_t)bmb * KT + c) * 16384, 16384u, mb);
        bulk_g2s(sbase + st * STG + 16384u, Bpk + (size_t)c * 16384,              16384u, mb);
    };
    if (tid == 0) { issue(0); issue(1); issue(2); }

    uint32_t acc[2][8][2];
    #pragma unroll
    for (int mi = 0; mi < 2; mi++)
        #pragma unroll
        for (int ni = 0; ni < 8; ni++) { acc[mi][ni][0] = 0u; acc[mi][ni][1] = 0u; }

    for (int kt = 0; kt < KT; kt++) {
        mbar_wait(mb0 + (kt % 3) * 8, (kt / 3) & 1);

        const unsigned as = sbase + (kt % 3) * STG;
        const unsigned bs = as + 16384u;
        #pragma unroll
        for (int s = 0; s < 4; s++) {
            unsigned af[2][4];
            #pragma unroll
            for (int mi = 0; mi < 2; mi++) {
                int row = wm + mi * 16 + (lane & 15);
                int ch  = 2 * s + (lane >> 4);
                unsigned addr = as + row * 128 + ((ch ^ (row & 7)) << 4);
                asm volatile("ldmatrix.sync.aligned.m8n8.x4.shared.b16 {%0,%1,%2,%3}, [%4];"
                    : "=r"(af[mi][0]), "=r"(af[mi][1]), "=r"(af[mi][2]), "=r"(af[mi][3])
                    : "r"(addr));
            }
            unsigned bf[8][2];
            #pragma unroll
            for (int nj = 0; nj < 4; nj++) {
                int row = wn + nj * 16 + (lane & 7) + ((lane & 16) >> 1);
                int ch  = 2 * s + ((lane >> 3) & 1);
                unsigned addr = bs + row * 128 + ((ch ^ (row & 7)) << 4);
                asm volatile("ldmatrix.sync.aligned.m8n8.x4.shared.b16 {%0,%1,%2,%3}, [%4];"
                    : "=r"(bf[2 * nj][0]), "=r"(bf[2 * nj][1]),
                      "=r"(bf[2 * nj + 1][0]), "=r"(bf[2 * nj + 1][1])
                    : "r"(addr));
            }
            #pragma unroll
            for (int mi = 0; mi < 2; mi++)
                #pragma unroll
                for (int ni = 0; ni < 8; ni++) {
                    asm volatile(
                        "mma.sync.aligned.m16n8k16.row.col.f16.f16.f16.f16 "
                        "{%0,%1}, {%2,%3,%4,%5}, {%6,%7}, {%0,%1};"
                        : "+r"(acc[mi][ni][0]), "+r"(acc[mi][ni][1])
                        : "r"(af[mi][0]), "r"(af[mi][1]), "r"(af[mi][2]), "r"(af[mi][3]),
                          "r"(bf[ni][0]), "r"(bf[ni][1]));
                }
        }
        __syncthreads();
        if (tid == 0 && kt + 3 < KT) issue(kt + 3);
    }

    const float scale = *scale_p;
    // wn=0 warps hold mu (cols 0..63), wn=64 warps hold log_std (cols 64..127).
    __syncthreads();                                  // pipeline smem now reusable
    constexpr int LSS = 65;
    float* ls_s  = (float*)smem;               // [128][65]
    float* std_s = ls_s + 128 * LSS;           // [128][65]
    if (wn == 64) {
        #pragma unroll
        for (int mi = 0; mi < 2; mi++) {
            const int rl = wm + mi * 16 + (lane >> 2);
            #pragma unroll
            for (int ni = 0; ni < 8; ni++) {
                const int c = ni * 8 + 2 * (lane & 3);
                float bz0 = __ldg(&bias[64 + c]), bz1 = __ldg(&bias[64 + c + 1]);
                float2 a01 = __half22float2(*reinterpret_cast<__half2*>(&acc[mi][ni][0]));
                float2 a23 = __half22float2(*reinterpret_cast<__half2*>(&acc[mi][ni][1]));
                float l0 = fminf(fmaxf(fmaf(a01.x, scale, bz0), -20.0f), 2.0f);
                float l1 = fminf(fmaxf(fmaf(a01.y, scale, bz1), -20.0f), 2.0f);
                float l2 = fminf(fmaxf(fmaf(a23.x, scale, bz0), -20.0f), 2.0f);
                float l3 = fminf(fmaxf(fmaf(a23.y, scale, bz1), -20.0f), 2.0f);
                ls_s[rl * LSS + c]           = l0;
                ls_s[rl * LSS + c + 1]       = l1;
                ls_s[(rl + 8) * LSS + c]     = l2;
                ls_s[(rl + 8) * LSS + c + 1] = l3;
                std_s[rl * LSS + c]           = expf(l0);
                std_s[rl * LSS + c + 1]       = expf(l1);
                std_s[(rl + 8) * LSS + c]     = expf(l2);
                std_s[(rl + 8) * LSS + c + 1] = expf(l3);
            }
        }
    }
    __syncthreads();
    if (wn == 0) {
        float lp[2][2] = {{0.0f, 0.0f}, {0.0f, 0.0f}};
        #pragma unroll
        for (int mi = 0; mi < 2; mi++) {
            const int rl = wm + mi * 16 + (lane >> 2);
            const int m0 = bm + rl, m1 = m0 + 8;
            #pragma unroll
            for (int ni = 0; ni < 8; ni++) {
                const int c = ni * 8 + 2 * (lane & 3);
                float bz0 = __ldg(&bias[c]), bz1 = __ldg(&bias[c + 1]);
                float2 e0 = *reinterpret_cast<const float2*>(eps + (size_t)m0 * ACT_D + c);
                float2 e1 = *reinterpret_cast<const float2*>(eps + (size_t)m1 * ACT_D + c);
                float2 a01 = __half22float2(*reinterpret_cast<__half2*>(&acc[mi][ni][0]));
                float2 a23 = __half22float2(*reinterpret_cast<__half2*>(&acc[mi][ni][1]));
                float mus[4] = {
                    fmaf(a01.x, scale, bz0), fmaf(a01.y, scale, bz1),
                    fmaf(a23.x, scale, bz0), fmaf(a23.y, scale, bz1)};
                const int rr[4] = {rl, rl, rl + 8, rl + 8};
                const int cc[4] = {c, c + 1, c, c + 1};
                const float ev[4] = {e0.x, e0.y, e1.x, e1.y};
                float av[4];
                #pragma unroll
                for (int e = 0; e < 4; e++) {
                    float sd = std_s[rr[e] * LSS + cc[e]];
                    float ls = ls_s[rr[e] * LSS + cc[e]];
                    float pi = fmaf(sd, ev[e], mus[e]);
                    av[e] = tanhf(pi);
                    float z  = -2.0f * pi;
                    float sp = fmaxf(z, 0.0f) + log1pf(expf(-fabsf(z)));
                    lp[mi][e >> 1] += fmaf(-0.5f * ev[e], ev[e], -ls)
                                    - 0.91893853320467274178f
                                    - 2.0f * (0.69314718055994530942f - pi - sp);
                }
                *reinterpret_cast<float2*>(action + (size_t)m0 * ACT_D + c) = make_float2(av[0], av[1]);
                *reinterpret_cast<float2*>(action + (size_t)m1 * ACT_D + c) = make_float2(av[2], av[3]);
            }
        }
        #pragma unroll
        for (int mi = 0; mi < 2; mi++)
            #pragma unroll
            for (int h = 0; h < 2; h++) {
                lp[mi][h] += __shfl_xor_sync(0xffffffffu, lp[mi][h], 1);
                lp[mi][h] += __shfl_xor_sync(0xffffffffu, lp[mi][h], 2);
            }
        if ((lane & 3) == 0) {
            #pragma unroll
            for (int mi = 0; mi < 2; mi++) {
                const int rl = wm + mi * 16 + (lane >> 2);
                logp[bm + rl]     = lp[mi][0];
                logp[bm + rl + 8] = lp[mi][1];
            }
        }
    }
}

// ---------------- launch ----------------
extern "C" void kernel_launch(void* const* d_in, const int* in_sizes, int n_in,
                              void* d_out, int out_size) {
    const float* obs = (const float*)d_in[0];
    const float* eps = (const float*)d_in[1];
    const float* W1  = (const float*)d_in[2];
    const float* b1  = (const float*)d_in[3];
    const float* W2  = (const float*)d_in[4];
    const float* b2  = (const float*)d_in[5];
    const float* W3  = (const float*)d_in[6];
    const float* b3  = (const float*)d_in[7];
    float* out = (float*)d_out;

    void *xb, *h1, *h2, *w1, *w2, *w3, *b1q, *b2q, *b3q, *sc;
    cudaGetSymbolAddress(&xb,  g_xb);
    cudaGetSymbolAddress(&h1,  g_h1);
    cudaGetSymbolAddress(&h2,  g_h2);
    cudaGetSymbolAddress(&w1,  g_w1);
    cudaGetSymbolAddress(&w2,  g_w2);
    cudaGetSymbolAddress(&w3,  g_w3);
    cudaGetSymbolAddress(&b1q, g_b1q);
    cudaGetSymbolAddress(&b2q, g_b2q);
    cudaGetSymbolAddress(&b3q, g_b3q);
    cudaGetSymbolAddress(&sc,  g_scales);

    const unsigned SM_BIG = 2u * 49152u;   // 96 KB, 2-stage -> occ 2
    const unsigned SM_FUS = 3u * 32768u;   // 96 KB, 3-stage -> occ 2
    cudaFuncSetAttribute((const void*)gemm_big,
                         cudaFuncAttributeMaxDynamicSharedMemorySize, SM_BIG);
    cudaFuncSetAttribute((const void*)gemm_fused,
                         cudaFuncAttributeMaxDynamicSharedMemorySize, SM_FUS);

    zero_absmax_kernel<<<1, 32>>>();
    absmax3_kernel<<<208, 256>>>((const float4*)W1, (const float4*)W2, (const float4*)W3);
    prep_kernel<<<1, 1024>>>(b1, b2, b3);
    quant3_pack_kernel<<<832, 256>>>(W1, W2, W3);
    cvt_obs_pack_kernel<<<(B_ROWS * OBS_D / 8) / 256, 256>>>(obs, (char*)xb);

    // layer 1: [32768,512] @ [1024,512]^T -> relu fp16 (x4096), packed out (KT=16)
    gemm_big<<<dim3(H1_D / 256, B_ROWS / 128), 256, SM_BIG>>>(
        (const char*)xb, (const char*)w1, (char*)h1,
        (const float*)b1q, (const float*)sc + 0, OBS_D / 64, H1_D / 64);

    // layer 2: [32768,1024] @ [1024,1024]^T -> relu fp16 (x4096), packed out (KT=16)
    gemm_big<<<dim3(H2_D / 256, B_ROWS / 128), 256, SM_BIG>>>(
        (const char*)h1, (const char*)w2, (char*)h2,
        (const float*)b2q, (const float*)sc + 1, H1_D / 64, H2_D / 64);

    // layer 3 fused with actor math: action + logp straight to d_out
    gemm_fused<<<dim3(1, B_ROWS / 128), 256, SM_FUS>>>(
        (const char*)h2, (const char*)w3,
        (const float*)b3q, (const float*)sc + 2,
        eps, out, out + (size_t)B_ROWS * ACT_D);
}